// round 1
// baseline (speedup 1.0000x reference)
#include <cuda_runtime.h>
#include <cuda_fp16.h>
#include <math.h>

// Problem constants (fixed shapes for this problem)
#define H   1024
#define FF  4096
#define E   8
#define T_MAX 8192

// GEMM tiling
#define BM 128
#define BN 64
#define BK 16

// ---------------- device scratch (no allocation allowed) ----------------
__device__ int   g_counts[E];
__device__ int   g_base[E];
__device__ int   g_list[E * T_MAX];          // packed token*2 + slot
__device__ float g_wts[T_MAX * 2];           // combine weight per (token, slot)
__device__ float g_act[(size_t)(2 * T_MAX) * FF];   // 256 MB: silu(x@w1^T)*(x@w3^T), grouped by expert
__device__ float g_ybuf[(size_t)T_MAX * 2 * H];     // 64 MB: per-slot expert outputs (pre-scaled)

// ---------------- kernels ----------------

__global__ void k_zero() {
    if (threadIdx.x < E) g_counts[threadIdx.x] = 0;
}

// One warp per token: fp32 logits, softmax, top-2, renorm, list build.
__global__ void k_router(const float* __restrict__ x,
                         const float* __restrict__ gate,
                         float* __restrict__ logits_out, int T) {
    __shared__ float sg[E * H];  // 32 KB
    for (int i = threadIdx.x; i < E * H; i += blockDim.x) sg[i] = gate[i];
    __syncthreads();

    int warp = threadIdx.x >> 5;
    int lane = threadIdx.x & 31;
    int t = blockIdx.x * 8 + warp;
    if (t >= T) return;

    const float* xr = x + (size_t)t * H;
    float acc[E];
#pragma unroll
    for (int e = 0; e < E; e++) acc[e] = 0.f;

    for (int k = lane; k < H; k += 32) {
        float xv = xr[k];
#pragma unroll
        for (int e = 0; e < E; e++) acc[e] += xv * sg[e * H + k];
    }
#pragma unroll
    for (int e = 0; e < E; e++) {
#pragma unroll
        for (int o = 16; o > 0; o >>= 1)
            acc[e] += __shfl_down_sync(0xffffffffu, acc[e], o);
    }

    if (lane == 0) {
#pragma unroll
        for (int e = 0; e < E; e++) logits_out[(size_t)t * E + e] = acc[e];

        // top-2 on logits (same ordering as on softmax probs); ties -> lower index
        int e0 = 0; float l0 = acc[0];
#pragma unroll
        for (int e = 1; e < E; e++) if (acc[e] > l0) { l0 = acc[e]; e0 = e; }
        int e1 = -1; float l1 = -1e30f;
#pragma unroll
        for (int e = 0; e < E; e++) if (e != e0 && acc[e] > l1) { l1 = acc[e]; e1 = e; }

        // softmax probs (fp32, max-subtracted), renormalized over the top-2
        float s = 0.f;
        float pe[E];
#pragma unroll
        for (int e = 0; e < E; e++) { pe[e] = expf(acc[e] - l0); s += pe[e]; }
        float p0 = pe[e0] / s, p1 = pe[e1] / s;
        float inv = 1.f / (p0 + p1);
        float w0 = p0 * inv, w1 = p1 * inv;

        int pos0 = atomicAdd(&g_counts[e0], 1);
        g_list[e0 * T_MAX + pos0] = (t << 1) | 0;
        g_wts[(t << 1) | 0] = w0;
        int pos1 = atomicAdd(&g_counts[e1], 1);
        g_list[e1 * T_MAX + pos1] = (t << 1) | 1;
        g_wts[(t << 1) | 1] = w1;
    }
}

__global__ void k_base() {
    if (threadIdx.x == 0 && blockIdx.x == 0) {
        int s = 0;
#pragma unroll
        for (int e = 0; e < E; e++) { g_base[e] = s; s += g_counts[e]; }
    }
}

// Fused up-projection: for expert e's tokens, act = silu(x@w1[e]^T) * (x@w3[e]^T).
// Grid: x = FF/BN, y = T_MAX/BM (early exit beyond count), z = expert.
__global__ __launch_bounds__(256) void k_gemm13(const float* __restrict__ x,
                                                const float* __restrict__ w1,
                                                const float* __restrict__ w3) {
    int e = blockIdx.z;
    int cnt = g_counts[e];
    int row0 = blockIdx.y * BM;
    if (row0 >= cnt) return;
    int n0 = blockIdx.x * BN;

    const float* W1 = w1 + (size_t)e * FF * H + (size_t)n0 * H;
    const float* W3 = w3 + (size_t)e * FF * H + (size_t)n0 * H;

    __shared__ __align__(16) float sA[BK][BM + 4];
    __shared__ __align__(16) float sB1[BK][BN + 4];
    __shared__ __align__(16) float sB3[BK][BN + 4];
    __shared__ int sTok[BM];

    for (int r = threadIdx.x; r < BM; r += 256)
        sTok[r] = (row0 + r < cnt) ? (g_list[e * T_MAX + row0 + r] >> 1) : -1;
    __syncthreads();

    int tid = threadIdx.x;
    int tx = tid & 15;   // 16 column groups of 4
    int ty = tid >> 4;   // 16 row groups of 8

    float acc1[8][4], acc3[8][4];
#pragma unroll
    for (int m = 0; m < 8; m++)
#pragma unroll
        for (int n = 0; n < 4; n++) { acc1[m][n] = 0.f; acc3[m][n] = 0.f; }

    for (int k0 = 0; k0 < H; k0 += BK) {
        // A: 128x16 (gathered rows), 8 elems/thread
#pragma unroll
        for (int i = 0; i < 8; i++) {
            int idx = i * 256 + tid;
            int r = idx >> 4, k = idx & 15;
            int tok = sTok[r];
            sA[k][r] = (tok >= 0) ? x[(size_t)tok * H + k0 + k] : 0.f;
        }
        // B1/B3: 64x16 each, 4 elems/thread each
#pragma unroll
        for (int i = 0; i < 4; i++) {
            int idx = i * 256 + tid;
            int r = idx >> 4, k = idx & 15;
            sB1[k][r] = W1[(size_t)r * H + k0 + k];
            sB3[k][r] = W3[(size_t)r * H + k0 + k];
        }
        __syncthreads();

#pragma unroll
        for (int kk = 0; kk < BK; kk++) {
            float4 a0 = *(const float4*)(&sA[kk][ty * 8]);
            float4 a1 = *(const float4*)(&sA[kk][ty * 8 + 4]);
            float4 b1 = *(const float4*)(&sB1[kk][tx * 4]);
            float4 b3 = *(const float4*)(&sB3[kk][tx * 4]);
            float a[8] = {a0.x, a0.y, a0.z, a0.w, a1.x, a1.y, a1.z, a1.w};
            float v1[4] = {b1.x, b1.y, b1.z, b1.w};
            float v3[4] = {b3.x, b3.y, b3.z, b3.w};
#pragma unroll
            for (int m = 0; m < 8; m++) {
#pragma unroll
                for (int n = 0; n < 4; n++) {
                    acc1[m][n] += a[m] * v1[n];
                    acc3[m][n] += a[m] * v3[n];
                }
            }
        }
        __syncthreads();
    }

    int base = g_base[e];
#pragma unroll
    for (int m = 0; m < 8; m++) {
        int r = ty * 8 + m;
        if (row0 + r < cnt) {
            size_t arow = (size_t)(base + row0 + r) * FF;
            float o[4];
#pragma unroll
            for (int n = 0; n < 4; n++) {
                float h1 = acc1[m][n];
                float sgm = 1.f / (1.f + expf(-h1));
                o[n] = (h1 * sgm) * acc3[m][n];
            }
            *(float4*)&g_act[arow + n0 + tx * 4] = make_float4(o[0], o[1], o[2], o[3]);
        }
    }
}

// Down-projection: y = act @ w2[e]^T, pre-scaled by combine weight, written to (token, slot).
__global__ __launch_bounds__(256) void k_gemm2(const float* __restrict__ w2) {
    int e = blockIdx.z;
    int cnt = g_counts[e];
    int row0 = blockIdx.y * BM;
    if (row0 >= cnt) return;
    int n0 = blockIdx.x * BN;   // over H
    int base = g_base[e];

    const float* W2 = w2 + (size_t)e * H * FF + (size_t)n0 * FF;
    const float* A = g_act + (size_t)base * FF;

    __shared__ __align__(16) float sA[BK][BM + 4];
    __shared__ __align__(16) float sB[BK][BN + 4];

    int tid = threadIdx.x;
    int tx = tid & 15;
    int ty = tid >> 4;

    float acc[8][4];
#pragma unroll
    for (int m = 0; m < 8; m++)
#pragma unroll
        for (int n = 0; n < 4; n++) acc[m][n] = 0.f;

    for (int k0 = 0; k0 < FF; k0 += BK) {
#pragma unroll
        for (int i = 0; i < 8; i++) {
            int idx = i * 256 + tid;
            int r = idx >> 4, k = idx & 15;
            sA[k][r] = (row0 + r < cnt) ? A[(size_t)(row0 + r) * FF + k0 + k] : 0.f;
        }
#pragma unroll
        for (int i = 0; i < 4; i++) {
            int idx = i * 256 + tid;
            int r = idx >> 4, k = idx & 15;
            sB[k][r] = W2[(size_t)r * FF + k0 + k];
        }
        __syncthreads();

#pragma unroll
        for (int kk = 0; kk < BK; kk++) {
            float4 a0 = *(const float4*)(&sA[kk][ty * 8]);
            float4 a1 = *(const float4*)(&sA[kk][ty * 8 + 4]);
            float4 bv = *(const float4*)(&sB[kk][tx * 4]);
            float a[8] = {a0.x, a0.y, a0.z, a0.w, a1.x, a1.y, a1.z, a1.w};
            float b[4] = {bv.x, bv.y, bv.z, bv.w};
#pragma unroll
            for (int m = 0; m < 8; m++)
#pragma unroll
                for (int n = 0; n < 4; n++) acc[m][n] += a[m] * b[n];
        }
        __syncthreads();
    }

#pragma unroll
    for (int m = 0; m < 8; m++) {
        int r = ty * 8 + m;
        if (row0 + r < cnt) {
            int ts = g_list[e * T_MAX + row0 + r];
            float w = g_wts[ts];
            size_t yrow = (size_t)ts * H;
            float o[4];
#pragma unroll
            for (int n = 0; n < 4; n++) o[n] = w * acc[m][n];
            *(float4*)&g_ybuf[yrow + n0 + tx * 4] = make_float4(o[0], o[1], o[2], o[3]);
        }
    }
}

// out[t, h] = ybuf[t, slot0, h] + ybuf[t, slot1, h]
__global__ void k_combine(float* __restrict__ out, int T) {
    int i = blockIdx.x * blockDim.x + threadIdx.x;     // over T*H/4
    int total = T * (H / 4);
    if (i >= total) return;
    int t = i / (H / 4);
    int h4 = i - t * (H / 4);
    const float4* yb = (const float4*)g_ybuf;
    float4 a = yb[(size_t)(2 * t) * (H / 4) + h4];
    float4 b = yb[(size_t)(2 * t + 1) * (H / 4) + h4];
    ((float4*)out)[i] = make_float4(a.x + b.x, a.y + b.y, a.z + b.z, a.w + b.w);
}

// ---------------- launch ----------------
extern "C" void kernel_launch(void* const* d_in, const int* in_sizes, int n_in,
                              void* d_out, int out_size) {
    // Inputs: hidden_states, gate_w, w1, w2, w3 (guard against gate/hidden swap by size)
    const float* x;
    const float* gate;
    if (in_sizes[0] > in_sizes[1]) { x = (const float*)d_in[0]; gate = (const float*)d_in[1]; }
    else                           { gate = (const float*)d_in[0]; x = (const float*)d_in[1]; }
    const float* w1 = (const float*)d_in[2];
    const float* w2 = (const float*)d_in[3];
    const float* w3 = (const float*)d_in[4];

    int T = (in_sizes[0] > in_sizes[1] ? in_sizes[0] : in_sizes[1]) / H;

    float* out = (float*)d_out;
    float* logits_out = out + (size_t)T * H;   // router_logits appended after moe output

    k_zero<<<1, 32>>>();
    k_router<<<(T + 7) / 8, 256>>>(x, gate, logits_out, T);
    k_base<<<1, 1>>>();

    dim3 g13(FF / BN, (T + BM - 1) / BM, E);
    k_gemm13<<<g13, 256>>>(x, w1, w3);

    dim3 g2(H / BN, (T + BM - 1) / BM, E);
    k_gemm2<<<g2, 256>>>(w2);

    int n4 = T * (H / 4);
    k_combine<<<(n4 + 255) / 256, 256>>>(out, T);
}